// round 16
// baseline (speedup 1.0000x reference)
#include <cuda_runtime.h>

// Problem constants (B=8, C=19, H=512, W=512)
#define CLS    19
#define NBINS  8192
#define HW     262144          // 512*512 = 2^18
#define PIX    2097152         // 8*HW

// Histograms TRANSPOSED: index = q*CLS + c  (spreads hot bins across all LTS slices)
__device__ unsigned int g_cntA[NBINS * CLS];
__device__ unsigned int g_cntB[NBINS * CLS];
__device__ double       g_loss[CLS];
__device__ unsigned int g_pres[CLS];
__device__ int          g_lab64;               // 1 if labels int64, 0 if int32

__global__ void zero_kernel() {
    int i = blockIdx.x * blockDim.x + threadIdx.x;
    if (i < NBINS * CLS) {
        g_cntA[i] = 0u;
        g_cntB[i] = 0u;
    }
}

// Detect label dtype: int64 labels 0..18 have all-zero odd 32-bit words.
__global__ void detect_kernel(const unsigned int* __restrict__ lab32) {
    __shared__ unsigned int s;
    if (threadIdx.x == 0) s = 0u;
    __syncthreads();
    unsigned int w = lab32[threadIdx.x * 2 + 1];
    for (int off = 16; off; off >>= 1)
        w |= __shfl_down_sync(0xffffffffu, w, off);
    if ((threadIdx.x & 31) == 0) atomicOr(&s, w);
    __syncthreads();
    if (threadIdx.x == 0) g_lab64 = (s == 0u) ? 1 : 0;
}

// Fused softmax + binning (round-15 structure; only the histogram layout is
// transposed to [bin][class] and the A-bin derived in integer form).
__global__ void __launch_bounds__(256) hist_kernel(const float* __restrict__ x,
                                                   const void* __restrict__ lab) {
    int p4 = blockIdx.x * blockDim.x + threadIdx.x;   // pixel-quad id
    if (p4 >= PIX / 4) return;
    int p  = p4 * 4;
    int b  = p >> 18;            // p / HW
    int hw = p & (HW - 1);
    size_t base = ((size_t)b * CLS) * (size_t)HW + (size_t)hw;

    float4 v[CLS];
    float4 s = make_float4(0.f, 0.f, 0.f, 0.f);
#pragma unroll
    for (int c = 0; c < CLS; c++) {
        float4 t = *(const float4*)(x + base + (size_t)c * HW);
        v[c].x = __expf(t.x); s.x += v[c].x;
        v[c].y = __expf(t.y); s.y += v[c].y;
        v[c].z = __expf(t.z); s.z += v[c].z;
        v[c].w = __expf(t.w); s.w += v[c].w;
    }
    float4 izN;
    izN.x = __fdividef((float)NBINS, s.x);
    izN.y = __fdividef((float)NBINS, s.y);
    izN.z = __fdividef((float)NBINS, s.z);
    izN.w = __fdividef((float)NBINS, s.w);

    int l0, l1, l2, l3;
    if (g_lab64) {
        const long long* L = (const long long*)lab;
        l0 = (int)L[p]; l1 = (int)L[p + 1]; l2 = (int)L[p + 2]; l3 = (int)L[p + 3];
    } else {
        int4 L = *(const int4*)((const int*)lab + p);
        l0 = L.x; l1 = L.y; l2 = L.z; l3 = L.w;
    }

#pragma unroll
    for (int c = 0; c < CLS; c++) {
        float eN[4] = { v[c].x * izN.x, v[c].y * izN.y,
                        v[c].z * izN.z, v[c].w * izN.w };
        int   ll[4] = { l0, l1, l2, l3 };
#pragma unroll
        for (int k = 0; k < 4; k++) {
            bool isA = (c == ll[k]);
            int qb = min((int)eN[k], NBINS - 1);     // B bin: floor(p*N), >= 0
            int q  = isA ? (NBINS - 1 - qb) : qb;    // A bin: floor((1-p)*N)
            unsigned int* h = isA ? g_cntA : g_cntB;
            atomicAdd(&h[q * CLS + c], 1u);          // RED.E.ADD.32 (no return)
        }
    }
}

// Per-class descending scan over bins; closed-form Lovasz loss.
// A-element with N B's above contributes e/(G+N); a bin's B-elements telescope:
// sum_{j=0}^{nB-1} 1/((GN+j)(GN+j+1)) = nB/(GN*(GN+nB)). Within-bin interleave
// by midpoint correction. fp32 per-bin math (GN<2^24 exact); fp64 accumulator.
__global__ void __launch_bounds__(1024) scan_kernel() {
    const int RPT = NBINS / 1024;   // 8 bins per thread
    int c = blockIdx.x;
    int t = threadIdx.x;
    int r0 = t * RPT;

    __shared__ unsigned int shA[1024];
    __shared__ unsigned int shB[1024];

    unsigned int cA[RPT], cB[RPT];
    unsigned int la = 0, lb = 0;
#pragma unroll
    for (int i = 0; i < RPT; i++) {
        int q = NBINS - 1 - (r0 + i);
        cA[i] = __ldg(&g_cntA[q * CLS + c]);
        cB[i] = __ldg(&g_cntB[q * CLS + c]);
        la += cA[i]; lb += cB[i];
    }
    shA[t] = la; shB[t] = lb;
    __syncthreads();

    for (int off = 1; off < 1024; off <<= 1) {
        unsigned int va = 0, vb = 0;
        if (t >= off) { va = shA[t - off]; vb = shB[t - off]; }
        __syncthreads();
        shA[t] += va; shB[t] += vb;
        __syncthreads();
    }
    unsigned int totA = shA[1023];
    unsigned int F = shA[t] - la;
    unsigned int N = shB[t] - lb;

    const float Gf = (float)totA;
    const float binw = 1.0f / (float)NBINS;
    double loss = 0.0;

#pragma unroll
    for (int i = 0; i < RPT; i++) {
        unsigned int nA = cA[i], nB = cB[i];
        if (nA | nB) {
            int q = NBINS - 1 - (r0 + i);
            float eq  = ((float)q + 0.5f) * binw;
            float fnA = (float)nA, fnB = (float)nB;
            float GN  = Gf + (float)N;
            float term = 0.0f;
            if (nA)
                term += fnA * eq * __fdividef(1.0f, GN + 0.5f * fnB);
            if (nB)
                term += eq * (Gf - (float)F - 0.5f * fnA) * fnB *
                        __fdividef(1.0f, GN * (GN + fnB));
            loss += (double)term;
            F += nA; N += nB;
        }
    }

    for (int off = 16; off; off >>= 1)
        loss += __shfl_down_sync(0xffffffffu, loss, off);
    __shared__ double warpS[32];
    if ((t & 31) == 0) warpS[t >> 5] = loss;
    __syncthreads();
    if (t < 32) {
        double v2 = warpS[t];
        for (int off = 16; off; off >>= 1)
            v2 += __shfl_down_sync(0xffffffffu, v2, off);
        if (t == 0) {
            g_loss[c] = v2;
            g_pres[c] = (totA > 0u) ? 1u : 0u;
        }
    }
}

__global__ void final_kernel(float* out) {
    int t = threadIdx.x;
    double l = 0.0, pcnt = 0.0;
    if (t < CLS && g_pres[t]) { l = g_loss[t]; pcnt = 1.0; }
    for (int off = 16; off; off >>= 1) {
        l    += __shfl_down_sync(0xffffffffu, l, off);
        pcnt += __shfl_down_sync(0xffffffffu, pcnt, off);
    }
    if (t == 0) out[0] = (float)(l / (pcnt > 0.0 ? pcnt : 1.0));
}

extern "C" void kernel_launch(void* const* d_in, const int* in_sizes, int n_in,
                              void* d_out, int out_size) {
    const float* x   = (const float*)d_in[0];
    const void*  lab = d_in[1];
    float*       out = (float*)d_out;

    (void)in_sizes; (void)n_in; (void)out_size;

    zero_kernel<<<(NBINS * CLS + 255) / 256, 256>>>();
    detect_kernel<<<1, 256>>>((const unsigned int*)lab);
    hist_kernel<<<(PIX / 4 + 255) / 256, 256>>>(x, lab);
    scan_kernel<<<CLS, 1024>>>();
    final_kernel<<<1, 32>>>(out);
}